// round 6
// baseline (speedup 1.0000x reference)
#include <cuda_runtime.h>
#include <cuda_bf16.h>
#include <cstdint>

// Problem constants
#define B 32
#define P 196
#define D 512
#define H 8
#define U 4
#define C 500

#define D4 128            // D / 4 (float4)
#define TOK_K 11
#define TOK_U 7
#define ROW_F4 (TOK_K * D4)   // 1408 float4 per known row

#define N_KNOWN   (16000LL * TOK_K * D)
#define OUT_UNK   (N_KNOWN)
#define N_UNK     ((long long)B * TOK_U * D)
#define OUT_SEM   (OUT_UNK + N_UNK)

// Scratch
__device__ float g_scores[B * P * H];
// g_mid[b] = [dom (512) | psem h=0..7 (8*512)] = middle 9 tokens, contiguous
__device__ float g_mid[B * 9 * D];
#define MID_F4 (9 * D4)   // 1152

// ---------------------------------------------------------------------------
// K1: scores[b][p][h]; grid = B*P, block = 256 (warp = head)
// ---------------------------------------------------------------------------
__global__ void k_scores(const float4* __restrict__ patch,
                         const float4* __restrict__ query) {
    int bp = blockIdx.x;
    int w = threadIdx.x >> 5, lane = threadIdx.x & 31;
    const float4* row = patch + (size_t)bp * D4;
    const float4* q = query + (size_t)w * D4;
    float acc = 0.f;
    #pragma unroll
    for (int k = 0; k < 4; k++) {
        float4 r = row[lane + 32 * k];
        float4 qq = q[lane + 32 * k];
        acc = fmaf(r.x, qq.x, acc);
        acc = fmaf(r.y, qq.y, acc);
        acc = fmaf(r.z, qq.z, acc);
        acc = fmaf(r.w, qq.w, acc);
    }
    #pragma unroll
    for (int o = 16; o; o >>= 1) acc += __shfl_xor_sync(0xffffffffu, acc, o);
    if (lane == 0) g_scores[(size_t)bp * H + w] = acc;
}

// ---------------------------------------------------------------------------
// K2: softmax + semantic tokens. grid=(B,4), block=128. p-loop MLP=7.
// ---------------------------------------------------------------------------
__global__ void k_tokens(const float* __restrict__ patch,
                         float* __restrict__ out_sem) {
    __shared__ float sw[P][H + 1];
    int b = blockIdx.x, dc = blockIdx.y;
    int tid = threadIdx.x;
    for (int i = tid; i < P * H; i += 128) {
        int p = i >> 3, h = i & 7;
        sw[p][h] = g_scores[(size_t)b * P * H + i];
    }
    __syncthreads();

    int w = tid >> 5, lane = tid & 31;
    for (int h = w; h < H; h += 4) {
        float mx = -3.4e38f;
        for (int p = lane; p < P; p += 32) mx = fmaxf(mx, sw[p][h]);
        #pragma unroll
        for (int o = 16; o; o >>= 1) mx = fmaxf(mx, __shfl_xor_sync(0xffffffffu, mx, o));
        float sum = 0.f;
        for (int p = lane; p < P; p += 32) {
            float e = expf(sw[p][h] - mx);
            sw[p][h] = e;
            sum += e;
        }
        #pragma unroll
        for (int o = 16; o; o >>= 1) sum += __shfl_xor_sync(0xffffffffu, sum, o);
        float inv = 1.f / sum;
        for (int p = lane; p < P; p += 32) sw[p][h] *= inv;
    }
    __syncthreads();

    int d = dc * 128 + tid;
    float acc[H];
    #pragma unroll
    for (int h = 0; h < H; h++) acc[h] = 0.f;
    const float* pb = patch + (size_t)b * P * D + d;
    // 196 = 7 * 28: unroll 7 -> 7 independent loads in flight per iteration
    #pragma unroll 7
    for (int p = 0; p < P; p++) {
        float x = pb[(size_t)p * D];
        #pragma unroll
        for (int h = 0; h < H; h++) acc[h] = fmaf(sw[p][h], x, acc[h]);
    }
    #pragma unroll
    for (int h = 0; h < H; h++)
        out_sem[((size_t)b * H + h) * D + d] = acc[h];
}

// ---------------------------------------------------------------------------
// K3: projected_domain -> g_mid[b][0:512]
// ---------------------------------------------------------------------------
__global__ void k_dom(const float* __restrict__ G,
                      const float* __restrict__ W,
                      const float* __restrict__ bias) {
    __shared__ float gs[D];
    int b = blockIdx.x, tid = threadIdx.x;
    gs[tid] = G[(size_t)b * D + tid];
    __syncthreads();
    int w = tid >> 5, lane = tid & 31;
    for (int g = 0; g < 8; g++) {
        int e = w * 32 + g * 4;
        float a0 = 0.f, a1 = 0.f, a2 = 0.f, a3 = 0.f;
        const float* w0 = W + (size_t)(e + 0) * D;
        const float* w1 = W + (size_t)(e + 1) * D;
        const float* w2 = W + (size_t)(e + 2) * D;
        const float* w3 = W + (size_t)(e + 3) * D;
        #pragma unroll 4
        for (int d = lane; d < D; d += 32) {
            float x = gs[d];
            a0 = fmaf(w0[d], x, a0);
            a1 = fmaf(w1[d], x, a1);
            a2 = fmaf(w2[d], x, a2);
            a3 = fmaf(w3[d], x, a3);
        }
        #pragma unroll
        for (int o = 16; o; o >>= 1) {
            a0 += __shfl_xor_sync(0xffffffffu, a0, o);
            a1 += __shfl_xor_sync(0xffffffffu, a1, o);
            a2 += __shfl_xor_sync(0xffffffffu, a2, o);
            a3 += __shfl_xor_sync(0xffffffffu, a3, o);
        }
        if (lane == 0) {
            g_mid[(size_t)b * (9 * D) + e + 0] = a0 + bias[e + 0];
            g_mid[(size_t)b * (9 * D) + e + 1] = a1 + bias[e + 1];
            g_mid[(size_t)b * (9 * D) + e + 2] = a2 + bias[e + 2];
            g_mid[(size_t)b * (9 * D) + e + 3] = a3 + bias[e + 3];
        }
    }
}

// ---------------------------------------------------------------------------
// K4: projected_sem -> g_mid[b][(1+h)*512 + e]  (R4 version: 17 us)
// ---------------------------------------------------------------------------
__global__ void k_sem(const float* __restrict__ S,
                      const float* __restrict__ W,
                      const float* __restrict__ bias) {
    __shared__ float ss[16][D];           // 32 KB
    int ec = blockIdx.x, h = blockIdx.y, b0 = blockIdx.z * 16;
    int tid = threadIdx.x, w = tid >> 5, lane = tid & 31;

    {
        const float4* S4 = (const float4*)S;
        float4* ss4 = (float4*)ss;
        for (int i = tid; i < 16 * D4; i += 256) {
            int bi = i >> 7, d4 = i & (D4 - 1);
            ss4[(size_t)bi * D4 + d4] = S4[(((size_t)(b0 + bi)) * H + h) * D4 + d4];
        }
    }
    __syncthreads();

    int e0 = ec * 16 + w * 2;
    const float* wr0 = W + ((size_t)h * D + e0 + 0) * D;
    const float* wr1 = W + ((size_t)h * D + e0 + 1) * D;
    float wa[16], wb[16];
    #pragma unroll
    for (int k = 0; k < 16; k++) {
        wa[k] = wr0[lane + 32 * k];
        wb[k] = wr1[lane + 32 * k];
    }
    float bv0 = bias[(size_t)h * D + e0 + 0];
    float bv1 = bias[(size_t)h * D + e0 + 1];

    for (int bg = 0; bg < 16; bg += 4) {
        float a00 = 0.f, a01 = 0.f, a02 = 0.f, a03 = 0.f;
        float a10 = 0.f, a11 = 0.f, a12 = 0.f, a13 = 0.f;
        #pragma unroll
        for (int k = 0; k < 16; k++) {
            int idx = lane + 32 * k;
            float s0 = ss[bg + 0][idx];
            float s1 = ss[bg + 1][idx];
            float s2 = ss[bg + 2][idx];
            float s3 = ss[bg + 3][idx];
            a00 = fmaf(wa[k], s0, a00);
            a01 = fmaf(wa[k], s1, a01);
            a02 = fmaf(wa[k], s2, a02);
            a03 = fmaf(wa[k], s3, a03);
            a10 = fmaf(wb[k], s0, a10);
            a11 = fmaf(wb[k], s1, a11);
            a12 = fmaf(wb[k], s2, a12);
            a13 = fmaf(wb[k], s3, a13);
        }
        #pragma unroll
        for (int o = 16; o; o >>= 1) {
            a00 += __shfl_xor_sync(0xffffffffu, a00, o);
            a01 += __shfl_xor_sync(0xffffffffu, a01, o);
            a02 += __shfl_xor_sync(0xffffffffu, a02, o);
            a03 += __shfl_xor_sync(0xffffffffu, a03, o);
            a10 += __shfl_xor_sync(0xffffffffu, a10, o);
            a11 += __shfl_xor_sync(0xffffffffu, a11, o);
            a12 += __shfl_xor_sync(0xffffffffu, a12, o);
            a13 += __shfl_xor_sync(0xffffffffu, a13, o);
        }
        if (lane == 0) {
            size_t r0 = ((size_t)(b0 + bg + 0)) * (9 * D) + (size_t)(1 + h) * D;
            size_t r1 = ((size_t)(b0 + bg + 1)) * (9 * D) + (size_t)(1 + h) * D;
            size_t r2 = ((size_t)(b0 + bg + 2)) * (9 * D) + (size_t)(1 + h) * D;
            size_t r3 = ((size_t)(b0 + bg + 3)) * (9 * D) + (size_t)(1 + h) * D;
            g_mid[r0 + e0] = a00 + bv0;  g_mid[r0 + e0 + 1] = a10 + bv1;
            g_mid[r1 + e0] = a01 + bv0;  g_mid[r1 + e0 + 1] = a11 + bv1;
            g_mid[r2 + e0] = a02 + bv0;  g_mid[r2 + e0 + 1] = a12 + bv1;
            g_mid[r3 + e0] = a03 + bv0;  g_mid[r3 + e0 + 1] = a13 + bv1;
        }
    }
}

// ---------------------------------------------------------------------------
// K5: known fill, 4 consecutive rows (same b) per block. Row-contiguous
// writes (R2-proven locality) + mid tokens held in registers across the
// 4 rows (4x less L2 read). All branches warp-uniform (128/256/384).
// grid = 32*125 = 4000, block = 512.
//
// Row layout (float4 idx): [0,128) pre | [128,1280) mid | [1280,1408) suf
// Thread t covers i = t, t+512, t+1024(<1408 iff t<384).
// ---------------------------------------------------------------------------
__global__ void k_fill4(const float4* __restrict__ pre,
                        const float4* __restrict__ suf,
                        float4* __restrict__ out_known) {
    int blk = blockIdx.x;
    int b = blk / 125, cg = blk - b * 125;
    int c0 = cg * 4;
    int t = threadIdx.x;
    const float4* gm = ((const float4*)g_mid) + (size_t)b * MID_F4;

    float4 v0, v2;
    if (t >= 128) v0 = __ldg(&gm[t - 128]);        // tokens 1..3
    float4 v1 = __ldg(&gm[t + 384]);               // tokens 4..7
    if (t < 256) v2 = __ldg(&gm[t + 896]);         // tokens 8..9

    float4* orow = out_known + ((size_t)b * C + c0) * ROW_F4;
    #pragma unroll
    for (int c = 0; c < 4; c++) {
        float4* o = orow + (size_t)c * ROW_F4;
        float4 first = (t < 128) ? __ldg(&pre[(size_t)(c0 + c) * D4 + t]) : v0;
        __stcs(&o[t], first);
        __stcs(&o[t + 512], v1);
        if (t < 384) {
            float4 last = (t < 256) ? v2
                        : __ldg(&suf[(size_t)(c0 + c) * D4 + (t - 256)]);
            __stcs(&o[t + 1024], last);
        }
    }
}

// ---------------------------------------------------------------------------
// K6: unknown prompts. grid = B, block = 128.
// ---------------------------------------------------------------------------
__global__ void k_fill_unk(const float4* __restrict__ upre,
                           const float4* __restrict__ usuf,
                           const float4* __restrict__ ust,
                           float4* __restrict__ out_unk) {
    int b = blockIdx.x, tid = threadIdx.x;
    const float4* gm = ((const float4*)g_mid) + (size_t)b * MID_F4;
    float4* o = out_unk + (size_t)b * (TOK_U * D4);
    for (int i = tid; i < TOK_U * D4; i += 128) {
        int t = i >> 7, d4 = i & (D4 - 1);
        float4 v;
        if (t == 0)      v = __ldg(&upre[d4]);
        else if (t == 1) v = __ldg(&gm[d4]);
        else if (t == 6) v = __ldg(&usuf[d4]);
        else             v = __ldg(&ust[(size_t)(t - 2) * D4 + d4]);
        o[i] = v;
    }
}

extern "C" void kernel_launch(void* const* d_in, const int* in_sizes, int n_in,
                              void* d_out, int out_size) {
    const float* patch = (const float*)d_in[0];
    const float* gfeat = (const float*)d_in[1];
    const float* query = (const float*)d_in[2];
    const float* domW  = (const float*)d_in[3];
    const float* domb  = (const float*)d_in[4];
    const float* semW  = (const float*)d_in[5];
    const float* semb  = (const float*)d_in[6];
    const float* ust   = (const float*)d_in[7];
    const float* kpre  = (const float*)d_in[8];
    const float* ksuf  = (const float*)d_in[9];
    const float* upre  = (const float*)d_in[10];
    const float* usuf  = (const float*)d_in[11];

    float* out = (float*)d_out;
    float* out_known = out;
    float* out_unk   = out + OUT_UNK;
    float* out_sem   = out + OUT_SEM;

    k_scores<<<B * P, 256>>>((const float4*)patch, (const float4*)query);
    k_dom<<<B, 512>>>(gfeat, domW, domb);
    k_tokens<<<dim3(B, 4), 128>>>(patch, out_sem);
    k_sem<<<dim3(32, H, 2), 256>>>(out_sem, semW, semb);
    k_fill4<<<4000, 512>>>((const float4*)kpre, (const float4*)ksuf,
                           (float4*)out_known);
    k_fill_unk<<<B, 128>>>((const float4*)upre, (const float4*)usuf,
                           (const float4*)ust, (float4*)out_unk);
}

// round 8
// speedup vs baseline: 1.3839x; 1.3839x over previous
#include <cuda_runtime.h>
#include <cuda_bf16.h>
#include <cstdint>

// Problem constants
#define B 32
#define P 196
#define D 512
#define H 8
#define U 4
#define C 500

#define D4 128            // D / 4 (float4)
#define TOK_K 11
#define TOK_U 7
#define ROW_F4 (TOK_K * D4)   // 1408 float4 per known row

#define N_KNOWN   (16000LL * TOK_K * D)
#define OUT_UNK   (N_KNOWN)
#define N_UNK     ((long long)B * TOK_U * D)
#define OUT_SEM   (OUT_UNK + N_UNK)

// Scratch
__device__ float g_scores[B * P * H];
// g_mid[b] = [dom (512) | psem h=0..7 (8*512)] = middle 9 tokens, contiguous
__device__ float g_mid[B * 9 * D];
#define MID_F4 (9 * D4)   // 1152

// ---------------------------------------------------------------------------
// K1: fused scores + domain projection.
// Blocks [0, B*P): scores[b][p][h] (warp = head, 8 warps).
// Blocks [B*P, B*P+B): projected_domain -> g_mid[b][0:512].
// block = 256.
// ---------------------------------------------------------------------------
__global__ void k_scores_dom(const float4* __restrict__ patch,
                             const float4* __restrict__ query,
                             const float* __restrict__ G,
                             const float* __restrict__ W,
                             const float* __restrict__ bias) {
    if (blockIdx.x < B * P) {
        int bp = blockIdx.x;
        int w = threadIdx.x >> 5, lane = threadIdx.x & 31;
        const float4* row = patch + (size_t)bp * D4;
        const float4* q = query + (size_t)w * D4;
        float acc = 0.f;
        #pragma unroll
        for (int k = 0; k < 4; k++) {
            float4 r = row[lane + 32 * k];
            float4 qq = q[lane + 32 * k];
            acc = fmaf(r.x, qq.x, acc);
            acc = fmaf(r.y, qq.y, acc);
            acc = fmaf(r.z, qq.z, acc);
            acc = fmaf(r.w, qq.w, acc);
        }
        #pragma unroll
        for (int o = 16; o; o >>= 1) acc += __shfl_xor_sync(0xffffffffu, acc, o);
        if (lane == 0) g_scores[(size_t)bp * H + w] = acc;
    } else {
        __shared__ float gs[D];
        int b = blockIdx.x - B * P;
        int tid = threadIdx.x;
        gs[tid] = G[(size_t)b * D + tid];
        gs[tid + 256] = G[(size_t)b * D + tid + 256];
        __syncthreads();
        int w = tid >> 5, lane = tid & 31;   // 8 warps, 64 e each
        for (int g = 0; g < 16; g++) {
            int e = w * 64 + g * 4;
            float a0 = 0.f, a1 = 0.f, a2 = 0.f, a3 = 0.f;
            const float* w0 = W + (size_t)(e + 0) * D;
            const float* w1 = W + (size_t)(e + 1) * D;
            const float* w2 = W + (size_t)(e + 2) * D;
            const float* w3 = W + (size_t)(e + 3) * D;
            #pragma unroll 4
            for (int d = lane; d < D; d += 32) {
                float x = gs[d];
                a0 = fmaf(w0[d], x, a0);
                a1 = fmaf(w1[d], x, a1);
                a2 = fmaf(w2[d], x, a2);
                a3 = fmaf(w3[d], x, a3);
            }
            #pragma unroll
            for (int o = 16; o; o >>= 1) {
                a0 += __shfl_xor_sync(0xffffffffu, a0, o);
                a1 += __shfl_xor_sync(0xffffffffu, a1, o);
                a2 += __shfl_xor_sync(0xffffffffu, a2, o);
                a3 += __shfl_xor_sync(0xffffffffu, a3, o);
            }
            if (lane == 0) {
                g_mid[(size_t)b * (9 * D) + e + 0] = a0 + bias[e + 0];
                g_mid[(size_t)b * (9 * D) + e + 1] = a1 + bias[e + 1];
                g_mid[(size_t)b * (9 * D) + e + 2] = a2 + bias[e + 2];
                g_mid[(size_t)b * (9 * D) + e + 3] = a3 + bias[e + 3];
            }
        }
    }
}

// ---------------------------------------------------------------------------
// K2: softmax + semantic tokens. grid=(B,4), block=128. p-loop MLP=7.
// ---------------------------------------------------------------------------
__global__ void k_tokens(const float* __restrict__ patch,
                         float* __restrict__ out_sem) {
    __shared__ float sw[P][H + 1];
    int b = blockIdx.x, dc = blockIdx.y;
    int tid = threadIdx.x;
    for (int i = tid; i < P * H; i += 128) {
        int p = i >> 3, h = i & 7;
        sw[p][h] = g_scores[(size_t)b * P * H + i];
    }
    __syncthreads();

    int w = tid >> 5, lane = tid & 31;
    for (int h = w; h < H; h += 4) {
        float mx = -3.4e38f;
        for (int p = lane; p < P; p += 32) mx = fmaxf(mx, sw[p][h]);
        #pragma unroll
        for (int o = 16; o; o >>= 1) mx = fmaxf(mx, __shfl_xor_sync(0xffffffffu, mx, o));
        float sum = 0.f;
        for (int p = lane; p < P; p += 32) {
            float e = expf(sw[p][h] - mx);
            sw[p][h] = e;
            sum += e;
        }
        #pragma unroll
        for (int o = 16; o; o >>= 1) sum += __shfl_xor_sync(0xffffffffu, sum, o);
        float inv = 1.f / sum;
        for (int p = lane; p < P; p += 32) sw[p][h] *= inv;
    }
    __syncthreads();

    int d = dc * 128 + tid;
    float acc[H];
    #pragma unroll
    for (int h = 0; h < H; h++) acc[h] = 0.f;
    const float* pb = patch + (size_t)b * P * D + d;
    #pragma unroll 7
    for (int p = 0; p < P; p++) {
        float x = pb[(size_t)p * D];
        #pragma unroll
        for (int h = 0; h < H; h++) acc[h] = fmaf(sw[p][h], x, acc[h]);
    }
    #pragma unroll
    for (int h = 0; h < H; h++)
        out_sem[((size_t)b * H + h) * D + d] = acc[h];
}

// ---------------------------------------------------------------------------
// K3: projected_sem -> g_mid[b][(1+h)*512 + e]  (R4-proven version)
// grid=(32 e-tiles of 16, H, 2 b-groups of 16), block=256, warp owns 2 e's.
// ---------------------------------------------------------------------------
__global__ void k_sem(const float* __restrict__ S,
                      const float* __restrict__ W,
                      const float* __restrict__ bias) {
    __shared__ float ss[16][D];           // 32 KB
    int ec = blockIdx.x, h = blockIdx.y, b0 = blockIdx.z * 16;
    int tid = threadIdx.x, w = tid >> 5, lane = tid & 31;

    {
        const float4* S4 = (const float4*)S;
        float4* ss4 = (float4*)ss;
        for (int i = tid; i < 16 * D4; i += 256) {
            int bi = i >> 7, d4 = i & (D4 - 1);
            ss4[(size_t)bi * D4 + d4] = S4[(((size_t)(b0 + bi)) * H + h) * D4 + d4];
        }
    }
    __syncthreads();

    int e0 = ec * 16 + w * 2;
    const float* wr0 = W + ((size_t)h * D + e0 + 0) * D;
    const float* wr1 = W + ((size_t)h * D + e0 + 1) * D;
    float wa[16], wb[16];
    #pragma unroll
    for (int k = 0; k < 16; k++) {
        wa[k] = wr0[lane + 32 * k];
        wb[k] = wr1[lane + 32 * k];
    }
    float bv0 = bias[(size_t)h * D + e0 + 0];
    float bv1 = bias[(size_t)h * D + e0 + 1];

    for (int bg = 0; bg < 16; bg += 4) {
        float a00 = 0.f, a01 = 0.f, a02 = 0.f, a03 = 0.f;
        float a10 = 0.f, a11 = 0.f, a12 = 0.f, a13 = 0.f;
        #pragma unroll
        for (int k = 0; k < 16; k++) {
            int idx = lane + 32 * k;
            float s0 = ss[bg + 0][idx];
            float s1 = ss[bg + 1][idx];
            float s2 = ss[bg + 2][idx];
            float s3 = ss[bg + 3][idx];
            a00 = fmaf(wa[k], s0, a00);
            a01 = fmaf(wa[k], s1, a01);
            a02 = fmaf(wa[k], s2, a02);
            a03 = fmaf(wa[k], s3, a03);
            a10 = fmaf(wb[k], s0, a10);
            a11 = fmaf(wb[k], s1, a11);
            a12 = fmaf(wb[k], s2, a12);
            a13 = fmaf(wb[k], s3, a13);
        }
        #pragma unroll
        for (int o = 16; o; o >>= 1) {
            a00 += __shfl_xor_sync(0xffffffffu, a00, o);
            a01 += __shfl_xor_sync(0xffffffffu, a01, o);
            a02 += __shfl_xor_sync(0xffffffffu, a02, o);
            a03 += __shfl_xor_sync(0xffffffffu, a03, o);
            a10 += __shfl_xor_sync(0xffffffffu, a10, o);
            a11 += __shfl_xor_sync(0xffffffffu, a11, o);
            a12 += __shfl_xor_sync(0xffffffffu, a12, o);
            a13 += __shfl_xor_sync(0xffffffffu, a13, o);
        }
        if (lane == 0) {
            size_t r0 = ((size_t)(b0 + bg + 0)) * (9 * D) + (size_t)(1 + h) * D;
            size_t r1 = ((size_t)(b0 + bg + 1)) * (9 * D) + (size_t)(1 + h) * D;
            size_t r2 = ((size_t)(b0 + bg + 2)) * (9 * D) + (size_t)(1 + h) * D;
            size_t r3 = ((size_t)(b0 + bg + 3)) * (9 * D) + (size_t)(1 + h) * D;
            g_mid[r0 + e0] = a00 + bv0;  g_mid[r0 + e0 + 1] = a10 + bv1;
            g_mid[r1 + e0] = a01 + bv0;  g_mid[r1 + e0 + 1] = a11 + bv1;
            g_mid[r2 + e0] = a02 + bv0;  g_mid[r2 + e0 + 1] = a12 + bv1;
            g_mid[r3 + e0] = a03 + bv0;  g_mid[r3 + e0 + 1] = a13 + bv1;
        }
    }
}

// ---------------------------------------------------------------------------
// K4: prompt fill — EXACT R2-winner structure. One block per row, direct
// __ldg source reads, __stcs row-contiguous writes, warp-uniform branches
// (128 and 1280 boundaries are warp-aligned at block=512).
// Blocks [0,16000): known row bc. Blocks [16000,16032): unknown row b.
// ---------------------------------------------------------------------------
__global__ void k_fill(const float4* __restrict__ pre,
                       const float4* __restrict__ suf,
                       const float4* __restrict__ upre,
                       const float4* __restrict__ usuf,
                       const float4* __restrict__ ust,
                       float4* __restrict__ out_known,
                       float4* __restrict__ out_unk) {
    int bc = blockIdx.x;
    if (bc < 16000) {
        int b = bc / C, c = bc - b * C;
        const float4* gm = ((const float4*)g_mid) + (size_t)b * MID_F4;
        const float4* pr = pre + (size_t)c * D4;
        const float4* su = suf + (size_t)c * D4;
        float4* o = out_known + (size_t)bc * ROW_F4;
        #pragma unroll
        for (int k = 0; k < 3; k++) {
            int i = threadIdx.x + k * 512;
            if (i < ROW_F4) {
                float4 v;
                if (i < 128)        v = __ldg(&pr[i]);
                else if (i < 1280)  v = __ldg(&gm[i - 128]);
                else                v = __ldg(&su[i - 1280]);
                __stcs(&o[i], v);
            }
        }
    } else {
        int b = bc - 16000;
        const float4* gm = ((const float4*)g_mid) + (size_t)b * MID_F4;
        float4* o = out_unk + (size_t)b * (TOK_U * D4);
        for (int i = threadIdx.x; i < TOK_U * D4; i += 512) {
            int t = i >> 7, d4 = i & (D4 - 1);
            float4 v;
            if (t == 0)      v = __ldg(&upre[d4]);
            else if (t == 1) v = __ldg(&gm[d4]);
            else if (t == 6) v = __ldg(&usuf[d4]);
            else             v = __ldg(&ust[(size_t)(t - 2) * D4 + d4]);
            __stcs(&o[i], v);
        }
    }
}

extern "C" void kernel_launch(void* const* d_in, const int* in_sizes, int n_in,
                              void* d_out, int out_size) {
    const float* patch = (const float*)d_in[0];
    const float* gfeat = (const float*)d_in[1];
    const float* query = (const float*)d_in[2];
    const float* domW  = (const float*)d_in[3];
    const float* domb  = (const float*)d_in[4];
    const float* semW  = (const float*)d_in[5];
    const float* semb  = (const float*)d_in[6];
    const float* ust   = (const float*)d_in[7];
    const float* kpre  = (const float*)d_in[8];
    const float* ksuf  = (const float*)d_in[9];
    const float* upre  = (const float*)d_in[10];
    const float* usuf  = (const float*)d_in[11];

    float* out = (float*)d_out;
    float* out_known = out;
    float* out_unk   = out + OUT_UNK;
    float* out_sem   = out + OUT_SEM;

    k_scores_dom<<<B * P + B, 256>>>((const float4*)patch, (const float4*)query,
                                     gfeat, domW, domb);
    k_tokens<<<dim3(B, 4), 128>>>(patch, out_sem);
    k_sem<<<dim3(32, H, 2), 256>>>(out_sem, semW, semb);
    k_fill<<<16032, 512>>>((const float4*)kpre, (const float4*)ksuf,
                           (const float4*)upre, (const float4*)usuf,
                           (const float4*)ust,
                           (float4*)out_known, (float4*)out_unk);
}

// round 9
// speedup vs baseline: 2.0918x; 1.5115x over previous
#include <cuda_runtime.h>
#include <cuda_bf16.h>
#include <cstdint>

// Problem constants
#define B 32
#define P 196
#define D 512
#define H 8
#define U 4
#define C 500

#define D4 128            // D / 4 (float4)
#define TOK_K 11
#define TOK_U 7
#define ROW_F4 (TOK_K * D4)   // 1408 float4 per known row

#define N_KNOWN   (16000LL * TOK_K * D)
#define OUT_UNK   (N_KNOWN)
#define N_UNK     ((long long)B * TOK_U * D)
#define OUT_SEM   (OUT_UNK + N_UNK)

// Scratch
__device__ float g_scores[B * P * H];
// g_mid[b] = [dom (512) | psem h=0..7 (8*512)] = middle 9 tokens, contiguous
__device__ float g_mid[B * 9 * D];
// p-split partial sums for semantic tokens: [pc][ (b*H+h)*D + d ]
__device__ float g_part[4][B * H * D];
#define MID_F4 (9 * D4)   // 1152

// ---------------------------------------------------------------------------
// K1: scores[b][p][h]; grid = B*P, block = 256 (warp = head)
// ---------------------------------------------------------------------------
__global__ void k_scores(const float4* __restrict__ patch,
                         const float4* __restrict__ query) {
    int bp = blockIdx.x;
    int w = threadIdx.x >> 5, lane = threadIdx.x & 31;
    const float4* row = patch + (size_t)bp * D4;
    const float4* q = query + (size_t)w * D4;
    float acc = 0.f;
    #pragma unroll
    for (int k = 0; k < 4; k++) {
        float4 r = row[lane + 32 * k];
        float4 qq = q[lane + 32 * k];
        acc = fmaf(r.x, qq.x, acc);
        acc = fmaf(r.y, qq.y, acc);
        acc = fmaf(r.z, qq.z, acc);
        acc = fmaf(r.w, qq.w, acc);
    }
    #pragma unroll
    for (int o = 16; o; o >>= 1) acc += __shfl_xor_sync(0xffffffffu, acc, o);
    if (lane == 0) g_scores[(size_t)bp * H + w] = acc;
}

// ---------------------------------------------------------------------------
// K2a: token partials. grid = (B, 4 d-chunks, 4 p-chunks), block = 128.
// Softmax over the FULL p range recomputed per block (cheap, 6 KB in smem);
// accumulation over this block's 49 p's only -> 4x parallelism + 4x shorter
// serial load chain vs one-shot version.
// ---------------------------------------------------------------------------
__global__ void k_tok_part(const float* __restrict__ patch) {
    __shared__ float sw[P][H + 1];
    int b = blockIdx.x, dc = blockIdx.y, pc = blockIdx.z;
    int tid = threadIdx.x;
    for (int i = tid; i < P * H; i += 128) {
        int p = i >> 3, h = i & 7;
        sw[p][h] = g_scores[(size_t)b * P * H + i];
    }
    __syncthreads();

    int w = tid >> 5, lane = tid & 31;
    for (int h = w; h < H; h += 4) {
        float mx = -3.4e38f;
        for (int p = lane; p < P; p += 32) mx = fmaxf(mx, sw[p][h]);
        #pragma unroll
        for (int o = 16; o; o >>= 1) mx = fmaxf(mx, __shfl_xor_sync(0xffffffffu, mx, o));
        float sum = 0.f;
        for (int p = lane; p < P; p += 32) {
            float e = expf(sw[p][h] - mx);
            sw[p][h] = e;
            sum += e;
        }
        #pragma unroll
        for (int o = 16; o; o >>= 1) sum += __shfl_xor_sync(0xffffffffu, sum, o);
        float inv = 1.f / sum;
        for (int p = lane; p < P; p += 32) sw[p][h] *= inv;
    }
    __syncthreads();

    int d = dc * 128 + tid;
    float acc[H];
    #pragma unroll
    for (int h = 0; h < H; h++) acc[h] = 0.f;
    const float* pb = patch + (size_t)b * P * D + d;
    int p0 = pc * 49;
    #pragma unroll 7
    for (int p = p0; p < p0 + 49; p++) {
        float x = pb[(size_t)p * D];
        #pragma unroll
        for (int h = 0; h < H; h++) acc[h] = fmaf(sw[p][h], x, acc[h]);
    }
    #pragma unroll
    for (int h = 0; h < H; h++)
        g_part[pc][((size_t)b * H + h) * D + d] = acc[h];
}

// ---------------------------------------------------------------------------
// K2b: reduce 4 p-chunk partials -> out_sem. 32768 float4; grid=128, blk=256.
// ---------------------------------------------------------------------------
__global__ void k_tok_red(float4* __restrict__ out_sem) {
    int i = blockIdx.x * 256 + threadIdx.x;
    const float4* p0 = (const float4*)g_part[0];
    const float4* p1 = (const float4*)g_part[1];
    const float4* p2 = (const float4*)g_part[2];
    const float4* p3 = (const float4*)g_part[3];
    float4 a = p0[i], bv = p1[i], c = p2[i], dv = p3[i];
    float4 r;
    r.x = (a.x + bv.x) + (c.x + dv.x);
    r.y = (a.y + bv.y) + (c.y + dv.y);
    r.z = (a.z + bv.z) + (c.z + dv.z);
    r.w = (a.w + bv.w) + (c.w + dv.w);
    out_sem[i] = r;
}

// ---------------------------------------------------------------------------
// K3: unified projection -> g_mid.
// y == 0: domain projection (src = global_features, W = dom_W) -> token 0.
// y >= 1: h = y-1 semantic projection (src = out_sem, W = sem_W[h]) -> token 1+h.
// grid = (32 e-tiles of 16, 9, 2 b-groups of 16), block = 256 (warp owns 2 e).
// Same proven R4 GEMM body; dom W now read 2x total instead of 32x.
// ---------------------------------------------------------------------------
__global__ void k_proj(const float* __restrict__ G,
                       const float* __restrict__ domW,
                       const float* __restrict__ domb,
                       const float* __restrict__ S,
                       const float* __restrict__ semW,
                       const float* __restrict__ semb) {
    __shared__ float ss[16][D];           // 32 KB
    int ec = blockIdx.x, y = blockIdx.y, b0 = blockIdx.z * 16;
    int tid = threadIdx.x, w = tid >> 5, lane = tid & 31;

    const float* W;
    const float* bias;
    int tok;
    if (y == 0) { W = domW; bias = domb; tok = 0; }
    else {
        int h = y - 1;
        W = semW + (size_t)h * D * D;
        bias = semb + (size_t)h * D;
        tok = 1 + y - 1 + 1;              // token index = 1 + h
        tok = y;                          // y = 1+h exactly
    }

    // stage 16 source rows
    {
        float4* ss4 = (float4*)ss;
        if (y == 0) {
            const float4* G4 = (const float4*)G;
            for (int i = tid; i < 16 * D4; i += 256) {
                int bi = i >> 7, d4 = i & (D4 - 1);
                ss4[(size_t)bi * D4 + d4] = G4[(size_t)(b0 + bi) * D4 + d4];
            }
        } else {
            int h = y - 1;
            const float4* S4 = (const float4*)S;
            for (int i = tid; i < 16 * D4; i += 256) {
                int bi = i >> 7, d4 = i & (D4 - 1);
                ss4[(size_t)bi * D4 + d4] = S4[(((size_t)(b0 + bi)) * H + h) * D4 + d4];
            }
        }
    }
    __syncthreads();

    int e0 = ec * 16 + w * 2;
    const float* wr0 = W + (size_t)(e0 + 0) * D;
    const float* wr1 = W + (size_t)(e0 + 1) * D;
    float wa[16], wb[16];
    #pragma unroll
    for (int k = 0; k < 16; k++) {
        wa[k] = wr0[lane + 32 * k];
        wb[k] = wr1[lane + 32 * k];
    }
    float bv0 = bias[e0 + 0];
    float bv1 = bias[e0 + 1];

    for (int bg = 0; bg < 16; bg += 4) {
        float a00 = 0.f, a01 = 0.f, a02 = 0.f, a03 = 0.f;
        float a10 = 0.f, a11 = 0.f, a12 = 0.f, a13 = 0.f;
        #pragma unroll
        for (int k = 0; k < 16; k++) {
            int idx = lane + 32 * k;
            float s0 = ss[bg + 0][idx];
            float s1 = ss[bg + 1][idx];
            float s2 = ss[bg + 2][idx];
            float s3 = ss[bg + 3][idx];
            a00 = fmaf(wa[k], s0, a00);
            a01 = fmaf(wa[k], s1, a01);
            a02 = fmaf(wa[k], s2, a02);
            a03 = fmaf(wa[k], s3, a03);
            a10 = fmaf(wb[k], s0, a10);
            a11 = fmaf(wb[k], s1, a11);
            a12 = fmaf(wb[k], s2, a12);
            a13 = fmaf(wb[k], s3, a13);
        }
        #pragma unroll
        for (int o = 16; o; o >>= 1) {
            a00 += __shfl_xor_sync(0xffffffffu, a00, o);
            a01 += __shfl_xor_sync(0xffffffffu, a01, o);
            a02 += __shfl_xor_sync(0xffffffffu, a02, o);
            a03 += __shfl_xor_sync(0xffffffffu, a03, o);
            a10 += __shfl_xor_sync(0xffffffffu, a10, o);
            a11 += __shfl_xor_sync(0xffffffffu, a11, o);
            a12 += __shfl_xor_sync(0xffffffffu, a12, o);
            a13 += __shfl_xor_sync(0xffffffffu, a13, o);
        }
        if (lane == 0) {
            size_t r0 = ((size_t)(b0 + bg + 0)) * (9 * D) + (size_t)tok * D;
            size_t r1 = ((size_t)(b0 + bg + 1)) * (9 * D) + (size_t)tok * D;
            size_t r2 = ((size_t)(b0 + bg + 2)) * (9 * D) + (size_t)tok * D;
            size_t r3 = ((size_t)(b0 + bg + 3)) * (9 * D) + (size_t)tok * D;
            g_mid[r0 + e0] = a00 + bv0;  g_mid[r0 + e0 + 1] = a10 + bv1;
            g_mid[r1 + e0] = a01 + bv0;  g_mid[r1 + e0 + 1] = a11 + bv1;
            g_mid[r2 + e0] = a02 + bv0;  g_mid[r2 + e0 + 1] = a12 + bv1;
            g_mid[r3 + e0] = a03 + bv0;  g_mid[r3 + e0 + 1] = a13 + bv1;
        }
    }
}

// ---------------------------------------------------------------------------
// K4: prompt fill — UNCHANGED R2/R8 winner (53.9 us @ 71% DRAM).
// ---------------------------------------------------------------------------
__global__ void k_fill(const float4* __restrict__ pre,
                       const float4* __restrict__ suf,
                       const float4* __restrict__ upre,
                       const float4* __restrict__ usuf,
                       const float4* __restrict__ ust,
                       float4* __restrict__ out_known,
                       float4* __restrict__ out_unk) {
    int bc = blockIdx.x;
    if (bc < 16000) {
        int b = bc / C, c = bc - b * C;
        const float4* gm = ((const float4*)g_mid) + (size_t)b * MID_F4;
        const float4* pr = pre + (size_t)c * D4;
        const float4* su = suf + (size_t)c * D4;
        float4* o = out_known + (size_t)bc * ROW_F4;
        #pragma unroll
        for (int k = 0; k < 3; k++) {
            int i = threadIdx.x + k * 512;
            if (i < ROW_F4) {
                float4 v;
                if (i < 128)        v = __ldg(&pr[i]);
                else if (i < 1280)  v = __ldg(&gm[i - 128]);
                else                v = __ldg(&su[i - 1280]);
                __stcs(&o[i], v);
            }
        }
    } else {
        int b = bc - 16000;
        const float4* gm = ((const float4*)g_mid) + (size_t)b * MID_F4;
        float4* o = out_unk + (size_t)b * (TOK_U * D4);
        for (int i = threadIdx.x; i < TOK_U * D4; i += 512) {
            int t = i >> 7, d4 = i & (D4 - 1);
            float4 v;
            if (t == 0)      v = __ldg(&upre[d4]);
            else if (t == 1) v = __ldg(&gm[d4]);
            else if (t == 6) v = __ldg(&usuf[d4]);
            else             v = __ldg(&ust[(size_t)(t - 2) * D4 + d4]);
            __stcs(&o[i], v);
        }
    }
}

extern "C" void kernel_launch(void* const* d_in, const int* in_sizes, int n_in,
                              void* d_out, int out_size) {
    const float* patch = (const float*)d_in[0];
    const float* gfeat = (const float*)d_in[1];
    const float* query = (const float*)d_in[2];
    const float* domW  = (const float*)d_in[3];
    const float* domb  = (const float*)d_in[4];
    const float* semW  = (const float*)d_in[5];
    const float* semb  = (const float*)d_in[6];
    const float* ust   = (const float*)d_in[7];
    const float* kpre  = (const float*)d_in[8];
    const float* ksuf  = (const float*)d_in[9];
    const float* upre  = (const float*)d_in[10];
    const float* usuf  = (const float*)d_in[11];

    float* out = (float*)d_out;
    float* out_known = out;
    float* out_unk   = out + OUT_UNK;
    float* out_sem   = out + OUT_SEM;

    k_scores<<<B * P, 256>>>((const float4*)patch, (const float4*)query);
    k_tok_part<<<dim3(B, 4, 4), 128>>>(patch);
    k_tok_red<<<128, 256>>>((float4*)out_sem);
    k_proj<<<dim3(32, 9, 2), 256>>>(gfeat, domW, domb, out_sem, semW, semb);
    k_fill<<<16032, 512>>>((const float4*)kpre, (const float4*)ksuf,
                           (const float4*)upre, (const float4*)usuf,
                           (const float4*)ust,
                           (float4*)out_known, (float4*)out_unk);
}